// round 3
// baseline (speedup 1.0000x reference)
#include <cuda_runtime.h>
#include <math.h>

#define NN 100000
#define NE 1600000
#define KT 25
#define XW_COLS 800   // KT*32

// ---------------- scratch (__device__ globals: allowed) ----------------
__device__ float g_xw[(size_t)NN * XW_COLS];   // [node][k*32+o]  320 MB
__device__ float g_xroot[NN * 32];
__device__ float g_rdot[NN];
__device__ float g_denom[NN];

// ---------------- K_root: x_root = x@rw, rdot = x_root . att[:32], init accumulators ----
__global__ void k_root(const float* __restrict__ x, const float* __restrict__ rw,
                       const float* __restrict__ att, float* __restrict__ out) {
    __shared__ float rws[1024];
    __shared__ float atts[32];
    int tid = threadIdx.x;
    for (int i = tid; i < 1024; i += 256) rws[i] = rw[i];
    if (tid < 32) atts[tid] = att[tid];
    __syncthreads();
    int warp = tid >> 5, lane = tid & 31;
    int n = blockIdx.x * 8 + warp;          // grid 12500 * 8 = 100000 exact
    float xv = x[n * 32 + lane];
    float acc = 0.f;
#pragma unroll
    for (int f = 0; f < 32; f++) {
        float xf = __shfl_sync(0xffffffffu, xv, f);
        acc = fmaf(xf, rws[f * 32 + lane], acc);
    }
    g_xroot[n * 32 + lane] = acc;
    out[n * 32 + lane] = 0.f;               // zero the edge accumulator (d_out)
    float t = acc * atts[lane];
#pragma unroll
    for (int o = 16; o; o >>= 1) t += __shfl_xor_sync(0xffffffffu, t, o);
    if (lane == 0) { g_rdot[n] = t; g_denom[n] = 0.f; }
}

// ---------------- K_xw: g_xw[n][k*32+o] = sum_f x[n][f] * W[k][f][o] ----------------
// block: 256 threads = (tx 0..15 cols-lane, ty 0..15 node-group)
// thread tile: 4 nodes (ty*4+j) x 8 cols (cc*128 + 16*i + tx)
#define WS_PAD 28672            // covers col<896, zero-padded past 25600
#define XS_STRIDE 33
#define K_XW_SMEM ((WS_PAD + 64 * XS_STRIDE) * 4)

__global__ void k_xw(const float* __restrict__ x, const float* __restrict__ w) {
    extern __shared__ float sm[];
    float* Ws = sm;                 // [k*1024 + f*32 + o]
    float* xs = sm + WS_PAD;        // [node_local * 33 + f]
    int tid = threadIdx.x;
    int n0 = blockIdx.x * 64;
    for (int i = tid; i < WS_PAD; i += 256) Ws[i] = (i < KT * 1024) ? w[i] : 0.f;
    for (int i = tid; i < 64 * 32; i += 256) {
        int n = i >> 5, f = i & 31;
        int gn = n0 + n;
        xs[n * XS_STRIDE + f] = (gn < NN) ? x[gn * 32 + f] : 0.f;
    }
    __syncthreads();
    int tx = tid & 15, ty = tid >> 4;

    for (int cc = 0; cc < 7; cc++) {
        int base[8];
#pragma unroll
        for (int i = 0; i < 8; i++) {
            int col = cc * 128 + 16 * i + tx;
            base[i] = (col >> 5) * 1024 + (col & 31);
        }
        float acc[4][8];
#pragma unroll
        for (int j = 0; j < 4; j++)
#pragma unroll
            for (int i = 0; i < 8; i++) acc[j][i] = 0.f;

#pragma unroll 8
        for (int f = 0; f < 32; f++) {
            float wv[8], xv[4];
#pragma unroll
            for (int i = 0; i < 8; i++) wv[i] = Ws[base[i] + f * 32];
#pragma unroll
            for (int j = 0; j < 4; j++) xv[j] = xs[(ty * 4 + j) * XS_STRIDE + f];
#pragma unroll
            for (int j = 0; j < 4; j++)
#pragma unroll
                for (int i = 0; i < 8; i++) acc[j][i] = fmaf(xv[j], wv[i], acc[j][i]);
        }
#pragma unroll
        for (int j = 0; j < 4; j++) {
            int n = n0 + ty * 4 + j;
            if (n < NN) {
                float* orow = g_xw + (size_t)n * XW_COLS;
#pragma unroll
                for (int i = 0; i < 8; i++) {
                    int col = cc * 128 + 16 * i + tx;
                    if (col < XW_COLS) orow[col] = acc[j][i];
                }
            }
        }
    }
}

// ---------------- K_edge: one pass over edges ----------------
// 8 threads per edge; lane q owns outputs [4q, 4q+4)
__global__ void k_edge(const int* __restrict__ ei, const float* __restrict__ ps,
                       const float* __restrict__ att, float* __restrict__ out) {
    int gid = blockIdx.x * 256 + threadIdx.x;   // 50000*256 = 12.8M = NE*8 exact
    int e = gid >> 3, q = gid & 7;
    int row = ei[e];
    int col = ei[NE + e];
    float2 p = *reinterpret_cast<const float2*>(ps + 2 * e);
    float p0 = p.x * 4.f, p1 = p.y * 4.f;
    float fl0 = floorf(p0), fl1 = floorf(p1);
    float fr0 = p0 - fl0, fr1 = p1 - fl1;
    int i0 = (int)fl0, i1 = (int)fl1;
    i0 = max(0, min(3, i0));
    i1 = max(0, min(3, i1));
    float b0 = (1.f - fr0) * (1.f - fr1);
    float b1 = fr0 * (1.f - fr1);
    float b2 = (1.f - fr0) * fr1;
    float b3 = fr0 * fr1;
    int w0 = i0 + 5 * i1;   // corners: w0, w0+1, w0+5, w0+6

    const float* xb = g_xw + (size_t)col * XW_COLS + q * 4;
    float4 m0 = *reinterpret_cast<const float4*>(xb + w0 * 32);
    float4 m1 = *reinterpret_cast<const float4*>(xb + (w0 + 1) * 32);
    float4 m2 = *reinterpret_cast<const float4*>(xb + (w0 + 5) * 32);
    float4 m3 = *reinterpret_cast<const float4*>(xb + (w0 + 6) * 32);
    float4 m;
    m.x = b0 * m0.x + b1 * m1.x + b2 * m2.x + b3 * m3.x;
    m.y = b0 * m0.y + b1 * m1.y + b2 * m2.y + b3 * m3.y;
    m.z = b0 * m0.z + b1 * m1.z + b2 * m2.z + b3 * m3.z;
    m.w = b0 * m0.w + b1 * m1.w + b2 * m2.w + b3 * m3.w;

    float4 av = __ldg(reinterpret_cast<const float4*>(att + 32) + q);
    float t = m.x * av.x + m.y * av.y + m.z * av.z + m.w * av.w;
    t += __shfl_xor_sync(0xffffffffu, t, 1);
    t += __shfl_xor_sync(0xffffffffu, t, 2);
    t += __shfl_xor_sync(0xffffffffu, t, 4);

    float alpha = g_rdot[row] + t;
    alpha = alpha > 0.f ? alpha : 0.2f * alpha;     // leaky relu
    float ex = expf(alpha);                          // no max-shift (see theory)
    if (q == 0) atomicAdd(&g_denom[row], ex);

    float* op = out + row * 32 + q * 4;
    asm volatile("red.global.add.v4.f32 [%0], {%1,%2,%3,%4};" ::
                 "l"(op), "f"(m.x * ex), "f"(m.y * ex), "f"(m.z * ex), "f"(m.w * ex)
                 : "memory");
}

// ---------------- K_fin: out = accum/denom + x_root + bias ----------------
__global__ void k_fin(float* __restrict__ out, const float* __restrict__ bias) {
    int i = blockIdx.x * 256 + threadIdx.x;  // 12500*256 = 3.2M exact
    int n = i >> 5, o = i & 31;
    out[i] = out[i] / (g_denom[n] + 1e-16f) + g_xroot[i] + bias[o];
}

// ---------------- launch ----------------
extern "C" void kernel_launch(void* const* d_in, const int* in_sizes, int n_in,
                              void* d_out, int out_size) {
    const float* x    = (const float*)d_in[0];
    const int*   ei   = (const int*)  d_in[1];
    const float* ps   = (const float*)d_in[2];
    const float* w    = (const float*)d_in[3];
    const float* rw   = (const float*)d_in[4];
    const float* att  = (const float*)d_in[5];
    const float* bias = (const float*)d_in[6];
    float* out = (float*)d_out;

    cudaFuncSetAttribute(k_xw, cudaFuncAttributeMaxDynamicSharedMemorySize, K_XW_SMEM);

    k_root<<<NN / 8, 256>>>(x, rw, att, out);
    k_xw<<<(NN + 63) / 64, 256, K_XW_SMEM>>>(x, w);
    k_edge<<<(NE * 8) / 256, 256>>>(ei, ps, att, out);
    k_fin<<<(NN * 32) / 256, 256>>>(out, bias);
}

// round 8
// speedup vs baseline: 1.1082x; 1.1082x over previous
#include <cuda_runtime.h>
#include <cuda_fp16.h>
#include <math.h>

#define NN 100000
#define NE 1600000
#define KT 25
#define XW_COLS 800   // KT*32

// ---------------- scratch (__device__ globals) ----------------
__device__ __half g_xw[(size_t)NN * XW_COLS];   // fp16 table, 160 MB
__device__ float g_xroot[NN * 32];
__device__ float g_rdot[NN];
__device__ float g_denom[NN];

// ---------------- f32x2 helpers ----------------
__device__ __forceinline__ void ffma2(unsigned long long& acc, unsigned long long a,
                                      unsigned long long b) {
    asm("fma.rn.f32x2 %0, %1, %2, %0;" : "+l"(acc) : "l"(a), "l"(b));
}
__device__ __forceinline__ unsigned long long pack2(float x, float y) {
    unsigned long long r;
    asm("mov.b64 %0, {%1,%2};" : "=l"(r) : "f"(x), "f"(y));
    return r;
}
__device__ __forceinline__ float2 unpack2(unsigned long long v) {
    float2 r;
    asm("mov.b64 {%0,%1}, %2;" : "=f"(r.x), "=f"(r.y) : "l"(v));
    return r;
}

// ---------------- K_root: x_root = x@rw, rdot, init accumulators ----------------
__global__ void k_root(const float* __restrict__ x, const float* __restrict__ rw,
                       const float* __restrict__ att, float* __restrict__ out) {
    __shared__ float rws[1024];
    __shared__ float atts[32];
    int tid = threadIdx.x;
    for (int i = tid; i < 1024; i += 256) rws[i] = rw[i];
    if (tid < 32) atts[tid] = att[tid];
    __syncthreads();
    int warp = tid >> 5, lane = tid & 31;
    int n = blockIdx.x * 8 + warp;          // 12500*8 = 100000 exact
    float xv = x[n * 32 + lane];
    float acc = 0.f;
#pragma unroll
    for (int f = 0; f < 32; f++) {
        float xf = __shfl_sync(0xffffffffu, xv, f);
        acc = fmaf(xf, rws[f * 32 + lane], acc);
    }
    g_xroot[n * 32 + lane] = acc;
    out[n * 32 + lane] = 0.f;               // zero edge accumulator
    float t = acc * atts[lane];
#pragma unroll
    for (int o = 16; o; o >>= 1) t += __shfl_xor_sync(0xffffffffu, t, o);
    if (lane == 0) { g_rdot[n] = t; g_denom[n] = 0.f; }
}

// ---------------- K_xw: g_xw[n][k*32+o] = sum_f x[n][f]*W[k][f][o]  (fp16 out) ----
// block 256: tx = tid&15 (8 contiguous cols each), ty = tid>>4 (8 nodes each)
// 128 nodes/block, 128 cols per cc-pass, 7 passes (896, padded past 800).
#define KB_STRIDE 1026                 // 1024 + 2 -> bank-shift 2 per k-block
#define NKB 28                         // covers col < 896
#define XS_STRIDE 33
#define WS_FLOATS (NKB * KB_STRIDE)    // 28728
#define K_XW_SMEM ((WS_FLOATS + 128 * XS_STRIDE) * 4)

__global__ void __launch_bounds__(256) k_xw(const float* __restrict__ x,
                                            const float* __restrict__ w) {
    extern __shared__ float sm[];
    float* Ws = sm;                    // [kb*1026 + f*32 + o]
    float* xs = sm + WS_FLOATS;        // [node_local*33 + f]
    int tid = threadIdx.x;
    int n0 = blockIdx.x * 128;

    // fill W (zero-pad kb>=25), vectorized
    for (int kb = 0; kb < NKB; kb++) {
        for (int i2 = tid; i2 < 513; i2 += 256) {
            float2 v = (kb < KT && i2 < 512) ? ((const float2*)w)[kb * 512 + i2]
                                             : make_float2(0.f, 0.f);
            *(float2*)&Ws[kb * KB_STRIDE + i2 * 2] = v;
        }
    }
    // fill x
    for (int i = tid; i < 128 * 32; i += 256) {
        int n = i >> 5, f = i & 31;
        int gn = n0 + n;
        xs[n * XS_STRIDE + f] = (gn < NN) ? x[gn * 32 + f] : 0.f;
    }
    __syncthreads();

    int tx = tid & 15, ty = tid >> 4;
    int coff = (tx * 8) & 31;                    // 0,8,16,24

    for (int cc = 0; cc < 7; cc++) {
        int col0 = cc * 128 + tx * 8;
        int base = (col0 >> 5) * KB_STRIDE + coff;

        unsigned long long acc[8][4];
#pragma unroll
        for (int j = 0; j < 8; j++)
#pragma unroll
            for (int i = 0; i < 4; i++) acc[j][i] = 0ull;

#pragma unroll
        for (int f = 0; f < 32; f++) {
            unsigned long long wp[4];
#pragma unroll
            for (int i = 0; i < 4; i++) {
                float2 w2 = *(const float2*)&Ws[base + f * 32 + 2 * i];
                wp[i] = pack2(w2.x, w2.y);
            }
#pragma unroll
            for (int j = 0; j < 8; j++) {
                float xv = xs[(ty * 8 + j) * XS_STRIDE + f];
                unsigned long long xp = pack2(xv, xv);
#pragma unroll
                for (int i = 0; i < 4; i++) ffma2(acc[j][i], xp, wp[i]);
            }
        }

        if (col0 < XW_COLS) {
#pragma unroll
            for (int j = 0; j < 8; j++) {
                int n = n0 + ty * 8 + j;
                if (n < NN) {
                    uint4 v;
                    float2 p0 = unpack2(acc[j][0]);
                    float2 p1 = unpack2(acc[j][1]);
                    float2 p2 = unpack2(acc[j][2]);
                    float2 p3 = unpack2(acc[j][3]);
                    __half2 h0 = __floats2half2_rn(p0.x, p0.y);
                    __half2 h1 = __floats2half2_rn(p1.x, p1.y);
                    __half2 h2 = __floats2half2_rn(p2.x, p2.y);
                    __half2 h3 = __floats2half2_rn(p3.x, p3.y);
                    v.x = *(unsigned int*)&h0;
                    v.y = *(unsigned int*)&h1;
                    v.z = *(unsigned int*)&h2;
                    v.w = *(unsigned int*)&h3;
                    *(uint4*)(g_xw + (size_t)n * XW_COLS + col0) = v;
                }
            }
        }
    }
}

// ---------------- K_edge: one pass over edges (fp16 gathers) ----------------
// 8 threads/edge; lane q owns outputs [4q, 4q+4)
__global__ void k_edge(const int* __restrict__ ei, const float* __restrict__ ps,
                       const float* __restrict__ att, float* __restrict__ out) {
    int gid = blockIdx.x * 256 + threadIdx.x;   // 50000*256 = NE*8 exact
    int e = gid >> 3, q = gid & 7;
    int row = ei[e];
    int col = ei[NE + e];
    float2 p = *reinterpret_cast<const float2*>(ps + 2 * e);
    float p0 = p.x * 4.f, p1 = p.y * 4.f;
    float fl0 = floorf(p0), fl1 = floorf(p1);
    float fr0 = p0 - fl0, fr1 = p1 - fl1;
    int i0 = (int)fl0, i1 = (int)fl1;
    i0 = max(0, min(3, i0));
    i1 = max(0, min(3, i1));
    float b0 = (1.f - fr0) * (1.f - fr1);
    float b1 = fr0 * (1.f - fr1);
    float b2 = (1.f - fr0) * fr1;
    float b3 = fr0 * fr1;
    int w0 = i0 + 5 * i1;   // corners: w0, w0+1, w0+5, w0+6

    // uint2 = 4 halves; index = col*200 + w*8 + q
    const uint2* tb = (const uint2*)g_xw;
    size_t nb = (size_t)col * 200 + q;
    uint2 u0 = __ldg(tb + nb + (size_t)w0 * 8);
    uint2 u1 = __ldg(tb + nb + (size_t)(w0 + 1) * 8);
    uint2 u2 = __ldg(tb + nb + (size_t)(w0 + 5) * 8);
    uint2 u3 = __ldg(tb + nb + (size_t)(w0 + 6) * 8);

    float2 a0 = __half22float2(*(__half2*)&u0.x), a1 = __half22float2(*(__half2*)&u0.y);
    float2 c0 = __half22float2(*(__half2*)&u1.x), c1 = __half22float2(*(__half2*)&u1.y);
    float2 d0 = __half22float2(*(__half2*)&u2.x), d1 = __half22float2(*(__half2*)&u2.y);
    float2 e0 = __half22float2(*(__half2*)&u3.x), e1 = __half22float2(*(__half2*)&u3.y);

    float4 m;
    m.x = b0 * a0.x + b1 * c0.x + b2 * d0.x + b3 * e0.x;
    m.y = b0 * a0.y + b1 * c0.y + b2 * d0.y + b3 * e0.y;
    m.z = b0 * a1.x + b1 * c1.x + b2 * d1.x + b3 * e1.x;
    m.w = b0 * a1.y + b1 * c1.y + b2 * d1.y + b3 * e1.y;

    float4 av = __ldg(reinterpret_cast<const float4*>(att + 32) + q);
    float t = m.x * av.x + m.y * av.y + m.z * av.z + m.w * av.w;
    t += __shfl_xor_sync(0xffffffffu, t, 1);
    t += __shfl_xor_sync(0xffffffffu, t, 2);
    t += __shfl_xor_sync(0xffffffffu, t, 4);

    float alpha = g_rdot[row] + t;
    alpha = alpha > 0.f ? alpha : 0.2f * alpha;     // leaky relu
    float ex = expf(alpha);                          // exact softmax w/o max-shift
    if (q == 0) atomicAdd(&g_denom[row], ex);

    float* op = out + row * 32 + q * 4;
    asm volatile("red.global.add.v4.f32 [%0], {%1,%2,%3,%4};" ::
                 "l"(op), "f"(m.x * ex), "f"(m.y * ex), "f"(m.z * ex), "f"(m.w * ex)
                 : "memory");
}

// ---------------- K_fin ----------------
__global__ void k_fin(float* __restrict__ out, const float* __restrict__ bias) {
    int i = blockIdx.x * 256 + threadIdx.x;  // 12500*256 = 3.2M exact
    int n = i >> 5, o = i & 31;
    out[i] = out[i] / (g_denom[n] + 1e-16f) + g_xroot[i] + bias[o];
}

// ---------------- launch ----------------
extern "C" void kernel_launch(void* const* d_in, const int* in_sizes, int n_in,
                              void* d_out, int out_size) {
    const float* x    = (const float*)d_in[0];
    const int*   ei   = (const int*)  d_in[1];
    const float* ps   = (const float*)d_in[2];
    const float* w    = (const float*)d_in[3];
    const float* rw   = (const float*)d_in[4];
    const float* att  = (const float*)d_in[5];
    const float* bias = (const float*)d_in[6];
    float* out = (float*)d_out;

    cudaFuncSetAttribute(k_xw, cudaFuncAttributeMaxDynamicSharedMemorySize, K_XW_SMEM);

    k_root<<<NN / 8, 256>>>(x, rw, att, out);
    k_xw<<<(NN + 127) / 128, 256, K_XW_SMEM>>>(x, w);
    k_edge<<<(NE * 8) / 256, 256>>>(ei, ps, att, out);
    k_fin<<<(NN * 32) / 256, 256>>>(out, bias);
}